// round 15
// baseline (speedup 1.0000x reference)
#include <cuda_runtime.h>
#include <cuda_bf16.h>
#include <math.h>
#include <stdint.h>

#define N_NODES 50000
#define N_EDGES 800000
#define IN_SIZE 256
#define OUT_SIZE 128
#define EDGE_DIM 64
#define SCAN_BLOCKS ((N_NODES + 255) / 256)   // 196

// ---------------- scratch (static device globals; no runtime allocation) ----
__device__ float g_proj[(size_t)N_NODES * 512];          // rows: [q|k|v|skip], stride 512
__device__ float g_qe[(size_t)N_NODES * EDGE_DIM];
__device__ float g_aggv[(size_t)N_NODES * OUT_SIZE];
__device__ float g_agge[(size_t)N_NODES * EDGE_DIM];
__device__ __nv_bfloat16 g_xhi[(size_t)N_NODES * IN_SIZE];
__device__ __nv_bfloat16 g_xlo[(size_t)N_NODES * IN_SIZE];
__device__ __nv_bfloat16 g_WTh[512 * 256];               // [n=512][k=256] = Wcat^T hi
__device__ __nv_bfloat16 g_WTl[512 * 256];
__device__ float g_bcat[512];
__device__ float g_WeT[128 * 64];                        // [K=128][N=64] = We^T
__device__ float g_zero128[128];
__device__ int   g_deg[N_NODES];
__device__ int   g_off[N_NODES + 1];
__device__ int   g_cur[N_NODES];
__device__ int   g_eorder[N_EDGES];
__device__ int   g_part[SCAN_BLOCKS];

__device__ __forceinline__ int clamp_node(int v) {
    return (v < 0) ? 0 : ((v >= N_NODES) ? N_NODES - 1 : v);
}
__device__ __forceinline__ uint32_t smem_u32(const void* p) {
    uint32_t a;
    asm("{ .reg .u64 t; cvta.to.shared.u64 t, %1; cvt.u32.u64 %0, t; }" : "=r"(a) : "l"(p));
    return a;
}

#define CPASYNC16(saddr, gptr) \
    asm volatile("cp.async.cg.shared.global [%0], [%1], 16;" :: "r"(saddr), "l"(gptr))
#define CP_COMMIT() asm volatile("cp.async.commit_group;" ::: "memory")
#define LDM4(d, addr) \
    asm volatile("ldmatrix.sync.aligned.m8n8.x4.shared.b16 {%0,%1,%2,%3}, [%4];" \
        : "=r"((d)[0]), "=r"((d)[1]), "=r"((d)[2]), "=r"((d)[3]) : "r"(addr))
#define MMA16816(c, a, b0v, b1v) \
    asm volatile("mma.sync.aligned.m16n8k16.row.col.f32.bf16.bf16.f32 " \
        "{%0,%1,%2,%3}, {%4,%5,%6,%7}, {%8,%9}, {%0,%1,%2,%3};" \
        : "+f"((c)[0]), "+f"((c)[1]), "+f"((c)[2]), "+f"((c)[3]) \
        : "r"((a)[0]), "r"((a)[1]), "r"((a)[2]), "r"((a)[3]), "r"(b0v), "r"(b1v))

// ---------------- bf16x3 tensor-core GEMM for node projections ---------------
#define NSTAGE 8            // 256 / 32
#define SROWB  80           // bytes per row slot (32 bf16 + 8 pad)
#define OFF_AH 0
#define OFF_AL 10240
#define OFF_BH 20480
#define OFF_BL 30720
#define BUFSZ  40960
#define MMA_SMEM (2 * BUFSZ)   // 81920

__global__ __launch_bounds__(256, 2) void gemm_mma(
    const __nv_bfloat16* __restrict__ Ahg, const __nv_bfloat16* __restrict__ Alg,
    const __nv_bfloat16* __restrict__ Bhg, const __nv_bfloat16* __restrict__ Blg,
    const float* __restrict__ bias, float* __restrict__ C)
{
    extern __shared__ char sm[];
    const uint32_t sb = smem_u32(sm);
    const int tid  = threadIdx.x;
    const int lane = tid & 31, wid = tid >> 5;
    const int wm = wid >> 1, wn = wid & 1;        // 4 x 2 warp grid
    const int row0 = blockIdx.y * 128;
    const int col0 = blockIdx.x * 128;

    float acc[2][8][4];
#pragma unroll
    for (int m = 0; m < 2; m++)
#pragma unroll
        for (int n = 0; n < 8; n++)
#pragma unroll
            for (int i = 0; i < 4; i++) acc[m][n][i] = 0.f;

    const int r8  = lane & 7, grp = lane >> 3;
    const int aRow = wm * 32 + ((grp & 1) << 3) + r8;
    const int aKel = (grp >> 1) << 3;
    const int bRow = wn * 64 + ((grp >> 1) << 3) + r8;
    const int bKel = (grp & 1) << 3;

#define LOAD_STAGE(s) do {                                                      \
        const int k0 = (s) * 32;                                                \
        const uint32_t bb = sb + ((s) & 1) * BUFSZ;                             \
        _Pragma("unroll")                                                       \
        for (int c = 0; c < 2; c++) {                                           \
            int idx = tid * 2 + c;                                              \
            int row = idx >> 2, sub = idx & 3;                                  \
            int gr = row0 + row; if (gr >= N_NODES) gr = N_NODES - 1;           \
            size_t gaoff = (size_t)gr * IN_SIZE + k0 + sub * 8;                 \
            uint32_t soff = row * SROWB + sub * 16;                             \
            CPASYNC16(bb + OFF_AH + soff, Ahg + gaoff);                         \
            CPASYNC16(bb + OFF_AL + soff, Alg + gaoff);                         \
            size_t gboff = (size_t)(col0 + row) * IN_SIZE + k0 + sub * 8;       \
            CPASYNC16(bb + OFF_BH + soff, Bhg + gboff);                         \
            CPASYNC16(bb + OFF_BL + soff, Blg + gboff);                         \
        }                                                                       \
        CP_COMMIT();                                                            \
    } while (0)

    LOAD_STAGE(0);

    for (int s = 0; s < NSTAGE; s++) {
        if (s + 1 < NSTAGE) {
            LOAD_STAGE(s + 1);
            asm volatile("cp.async.wait_group 1;" ::: "memory");
        } else {
            asm volatile("cp.async.wait_group 0;" ::: "memory");
        }
        __syncthreads();

        const uint32_t bb = sb + (s & 1) * BUFSZ;
#pragma unroll
        for (int ks = 0; ks < 32; ks += 16) {
            uint32_t ah[2][4], al[2][4];
#pragma unroll
            for (int mt = 0; mt < 2; mt++) {
                uint32_t ad = bb + OFF_AH + (aRow + mt * 16) * SROWB + (aKel + ks) * 2;
                LDM4(ah[mt], ad);
                LDM4(al[mt], ad + (OFF_AL - OFF_AH));
            }
#pragma unroll
            for (int p = 0; p < 4; p++) {
                uint32_t bh[4], bl[4];
                uint32_t bd = bb + OFF_BH + (bRow + p * 16) * SROWB + (bKel + ks) * 2;
                LDM4(bh, bd);
                LDM4(bl, bd + (OFF_BL - OFF_BH));
#pragma unroll
                for (int mt = 0; mt < 2; mt++) {
#pragma unroll
                    for (int t = 0; t < 2; t++) {
                        float* cc = acc[mt][p * 2 + t];
                        MMA16816(cc, ah[mt], bh[2 * t], bh[2 * t + 1]);
                        MMA16816(cc, ah[mt], bl[2 * t], bl[2 * t + 1]);
                        MMA16816(cc, al[mt], bh[2 * t], bh[2 * t + 1]);
                    }
                }
            }
        }
        __syncthreads();
    }

#pragma unroll
    for (int mt = 0; mt < 2; mt++) {
        int r = row0 + wm * 32 + mt * 16 + (lane >> 2);
#pragma unroll
        for (int p = 0; p < 8; p++) {
            int col = col0 + wn * 64 + p * 8 + (lane & 3) * 2;
            float b0 = __ldg(bias + col), b1 = __ldg(bias + col + 1);
            if (r < N_NODES) {
                float2 o = make_float2(acc[mt][p][0] + b0, acc[mt][p][1] + b1);
                *(float2*)(C + (size_t)r * 512 + col) = o;
            }
            if (r + 8 < N_NODES) {
                float2 o = make_float2(acc[mt][p][2] + b0, acc[mt][p][3] + b1);
                *(float2*)(C + (size_t)(r + 8) * 512 + col) = o;
            }
        }
    }
#undef LOAD_STAGE
}

// ---------------- small-K projection GEMM (B fully in smem, one sync) --------
// C[M,N] = A[M,K](lda) @ B[K,N] + bias (+add1/+add2, elu). 256 threads.
// ROWS rows per block; thread computes N/(256/ROWS) contiguous cols of one row.
template <int ROWS, int K, int N>
__global__ __launch_bounds__(256) void proj_small(
    const float* __restrict__ A, int lda,
    const float* __restrict__ B,
    const float* __restrict__ bias, float* __restrict__ C, int ldc,
    const float* __restrict__ add1, int as1,
    const float* __restrict__ add2, int as2,
    int do_elu, int M)
{
    static_assert(256 % ROWS == 0, "");
    static_assert((ROWS * N) % 256 == 0, "");
    constexpr int TPR = 256 / ROWS;      // threads per row
    constexpr int CPT = N / TPR;         // cols per thread
    static_assert(CPT % 4 == 0, "float4 tiles");
    constexpr int KP = K + 4;            // padded A row (bank-conflict kill)

    __shared__ float Bs[K * N];
    __shared__ float As[ROWS * KP];

    const int tid  = threadIdx.x;
    const int row0 = blockIdx.x * ROWS;

    // load B (K*N floats, coalesced float4)
#pragma unroll
    for (int i = 0; i < (K * N) / (256 * 4); i++) {
        int f = tid + i * 256;
        *(float4*)&Bs[f * 4] = *(const float4*)(B + f * 4);
    }
    // load A rows (guarded)
#pragma unroll
    for (int i = 0; i < (ROWS * K) / (256 * 4); i++) {
        int f = tid + i * 256;
        int r = f / (K / 4);
        int kk = (f % (K / 4)) * 4;
        int gr = row0 + r;
        float4 v = make_float4(0.f, 0.f, 0.f, 0.f);
        if (gr < M) v = *(const float4*)(A + (size_t)gr * lda + kk);
        *(float4*)&As[r * KP + kk] = v;
    }
    __syncthreads();

    const int r  = tid / TPR;
    const int c0 = (tid % TPR) * CPT;

    float acc[CPT];
#pragma unroll
    for (int j = 0; j < CPT; j++) acc[j] = 0.f;

#pragma unroll 4
    for (int k = 0; k < K; k++) {
        const float a = As[r * KP + k];
#pragma unroll
        for (int j = 0; j < CPT; j += 4) {
            float4 b = *(float4*)&Bs[k * N + c0 + j];
            acc[j + 0] = fmaf(a, b.x, acc[j + 0]);
            acc[j + 1] = fmaf(a, b.y, acc[j + 1]);
            acc[j + 2] = fmaf(a, b.z, acc[j + 2]);
            acc[j + 3] = fmaf(a, b.w, acc[j + 3]);
        }
    }

    const int gr = row0 + r;
    if (gr < M) {
#pragma unroll
        for (int j = 0; j < CPT; j += 4) {
            int c = c0 + j;
            float4 o;
            o.x = acc[j + 0] + bias[c + 0];
            o.y = acc[j + 1] + bias[c + 1];
            o.z = acc[j + 2] + bias[c + 2];
            o.w = acc[j + 3] + bias[c + 3];
            if (add1) {
                float4 a1 = *(const float4*)(add1 + (size_t)gr * as1 + c);
                o.x += a1.x; o.y += a1.y; o.z += a1.z; o.w += a1.w;
            }
            if (add2) {
                float4 a2 = *(const float4*)(add2 + (size_t)gr * as2 + c);
                o.x += a2.x; o.y += a2.y; o.z += a2.z; o.w += a2.w;
            }
            if (do_elu) {
                o.x = (o.x > 0.f) ? o.x : expm1f(o.x);
                o.y = (o.y > 0.f) ? o.y : expm1f(o.y);
                o.z = (o.z > 0.f) ? o.z : expm1f(o.z);
                o.w = (o.w > 0.f) ? o.w : expm1f(o.w);
            }
            *(float4*)(C + (size_t)gr * ldc + c) = o;
        }
    }
}

// ---------------- prep kernels ------------------------------------------------
__global__ void split_x_kernel(const float* __restrict__ x) {
    int i = blockIdx.x * blockDim.x + threadIdx.x;
    if (i < N_NODES * IN_SIZE / 4) {
        float4 v = ((const float4*)x)[i];
        __nv_bfloat16 hx = __float2bfloat16(v.x), hy = __float2bfloat16(v.y);
        __nv_bfloat16 hz = __float2bfloat16(v.z), hw = __float2bfloat16(v.w);
        __nv_bfloat16 lx = __float2bfloat16(v.x - __bfloat162float(hx));
        __nv_bfloat16 ly = __float2bfloat16(v.y - __bfloat162float(hy));
        __nv_bfloat16 lz = __float2bfloat16(v.z - __bfloat162float(hz));
        __nv_bfloat16 lw = __float2bfloat16(v.w - __bfloat162float(hw));
        __nv_bfloat162 h01 = __halves2bfloat162(hx, hy), h23 = __halves2bfloat162(hz, hw);
        __nv_bfloat162 l01 = __halves2bfloat162(lx, ly), l23 = __halves2bfloat162(lz, lw);
        ((uint2*)g_xhi)[i] = make_uint2(*(uint32_t*)&h01, *(uint32_t*)&h23);
        ((uint2*)g_xlo)[i] = make_uint2(*(uint32_t*)&l01, *(uint32_t*)&l23);
    }
}

__global__ void prep_weights(const float* __restrict__ Wq, const float* __restrict__ Wk,
                             const float* __restrict__ Wv, const float* __restrict__ Ws,
                             const float* __restrict__ bq, const float* __restrict__ bk,
                             const float* __restrict__ bv, const float* __restrict__ bs,
                             const float* __restrict__ We) {
    int idx = blockIdx.x * blockDim.x + threadIdx.x;
    if (idx < 512 * 256) {
        int col = idx / 256, k = idx % 256;
        int g = col / 128, n = col % 128;
        const float* W = (g == 0) ? Wq : (g == 1) ? Wk : (g == 2) ? Wv : Ws;
        float v = W[k * 128 + n];
        __nv_bfloat16 hi = __float2bfloat16(v);
        __nv_bfloat16 lo = __float2bfloat16(v - __bfloat162float(hi));
        g_WTh[col * 256 + k] = hi;
        g_WTl[col * 256 + k] = lo;
    }
    if (idx < 512) {
        const float* b = (idx < 128) ? bq : (idx < 256) ? bk : (idx < 384) ? bv : bs;
        g_bcat[idx] = b[idx % 128];
    }
    if (idx < 128 * 64) {
        int c = idx / 64, d = idx % 64;
        g_WeT[c * 64 + d] = We[d * 128 + c];
    }
    if (idx < 128) g_zero128[idx] = 0.f;
    if (idx < N_NODES) g_deg[idx] = 0;     // fused zero_deg
}

// ---------------- CSR build ---------------------------------------------------
__global__ void count_kernel(const int* __restrict__ edge_index) {
    int i = blockIdx.x * blockDim.x + threadIdx.x;
    if (i < N_EDGES) atomicAdd(&g_deg[clamp_node(edge_index[N_EDGES + i])], 1);
}
__global__ __launch_bounds__(256) void reduce_deg_kernel() {
    __shared__ int sm[256];
    int t = threadIdx.x;
    int i = blockIdx.x * 256 + t;
    sm[t] = (i < N_NODES) ? g_deg[i] : 0;
    __syncthreads();
#pragma unroll
    for (int s = 128; s > 0; s >>= 1) {
        if (t < s) sm[t] += sm[t + s];
        __syncthreads();
    }
    if (t == 0) g_part[blockIdx.x] = sm[0];
}
__global__ __launch_bounds__(256) void scan_parts_kernel() {
    __shared__ int sp[256];
    int t = threadIdx.x;
    int v = (t < SCAN_BLOCKS) ? g_part[t] : 0;
    sp[t] = v;
    __syncthreads();
#pragma unroll
    for (int off = 1; off < 256; off <<= 1) {
        int u = (t >= off) ? sp[t - off] : 0;
        __syncthreads();
        sp[t] += u;
        __syncthreads();
    }
    if (t < SCAN_BLOCKS) g_part[t] = sp[t] - v;
}
__global__ __launch_bounds__(256) void write_off_kernel() {
    __shared__ int sc[256];
    int t = threadIdx.x;
    int i = blockIdx.x * 256 + t;
    int d = (i < N_NODES) ? g_deg[i] : 0;
    sc[t] = d;
    __syncthreads();
#pragma unroll
    for (int off = 1; off < 256; off <<= 1) {
        int u = (t >= off) ? sc[t - off] : 0;
        __syncthreads();
        sc[t] += u;
        __syncthreads();
    }
    int excl = sc[t] - d + g_part[blockIdx.x];
    if (i < N_NODES) {
        g_off[i] = excl;
        g_cur[i] = excl;
        if (i == N_NODES - 1) g_off[N_NODES] = excl + d;
    }
}
__global__ void scatter_kernel(const int* __restrict__ edge_index) {
    int i = blockIdx.x * blockDim.x + threadIdx.x;
    if (i < N_EDGES) {
        int dst = clamp_node(edge_index[N_EDGES + i]);
        int p = atomicAdd(&g_cur[dst], 1);
        if (p >= 0 && p < N_EDGES) g_eorder[p] = i;
    }
}

// ---------------- fused attention (R8: one warp/node, 2-edge unrolled) --------
__global__ __launch_bounds__(256) void attn_kernel(
    const int* __restrict__ edge_index, const float* __restrict__ edge_attr,
    const float* __restrict__ be)
{
    const int warp = threadIdx.x / 32;
    const int lane = threadIdx.x % 32;
    const int node = blockIdx.x * 8 + warp;
    if (node >= N_NODES) return;

    const float* prow = g_proj + (size_t)node * 512;
    const float4 qv = __ldg((const float4*)(prow + lane * 4));
    const float2 qe = __ldg((const float2*)(g_qe + (size_t)node * 64 + lane * 2));

    float4 accv = make_float4(0.f, 0.f, 0.f, 0.f);
    float2 acce = make_float2(0.f, 0.f);
    float m = -INFINITY;
    float s = 0.f;

    int beg = g_off[node];
    int end = g_off[node + 1];
    if (beg < 0) beg = 0;
    if (end > N_EDGES) end = N_EDGES;

    int p = beg;
    for (; p + 1 < end; p += 2) {
        const int ei0  = __ldg(&g_eorder[p]);
        const int ei1  = __ldg(&g_eorder[p + 1]);
        const int src0 = clamp_node(__ldg(&edge_index[ei0]));
        const int src1 = clamp_node(__ldg(&edge_index[ei1]));

        const float* s0 = g_proj + (size_t)src0 * 512;
        const float* s1 = g_proj + (size_t)src1 * 512;
        const float4 kv0 = __ldg((const float4*)(s0 + 128 + lane * 4));
        const float4 kv1 = __ldg((const float4*)(s1 + 128 + lane * 4));
        const float4 vv0 = __ldg((const float4*)(s0 + 256 + lane * 4));
        const float4 vv1 = __ldg((const float4*)(s1 + 256 + lane * 4));
        const float2 ea0 = __ldg((const float2*)(edge_attr + (size_t)ei0 * 64 + lane * 2));
        const float2 ea1 = __ldg((const float2*)(edge_attr + (size_t)ei1 * 64 + lane * 2));

        float d0 = fmaf(qv.x, kv0.x, fmaf(qv.y, kv0.y, fmaf(qv.z, kv0.z,
                   fmaf(qv.w, kv0.w, fmaf(qe.x, ea0.x, qe.y * ea0.y)))));
        float d1 = fmaf(qv.x, kv1.x, fmaf(qv.y, kv1.y, fmaf(qv.z, kv1.z,
                   fmaf(qv.w, kv1.w, fmaf(qe.x, ea1.x, qe.y * ea1.y)))));
#pragma unroll
        for (int off = 16; off > 0; off >>= 1) {
            d0 += __shfl_xor_sync(0xFFFFFFFFu, d0, off);
            d1 += __shfl_xor_sync(0xFFFFFFFFu, d1, off);
        }

        const float a0 = d0 * 0.08838834764831845f;   // 1/sqrt(128)
        const float a1 = d1 * 0.08838834764831845f;
        const float nm = fmaxf(m, fmaxf(a0, a1));
        const float f  = __expf(m - nm);              // 0 on first pair (m = -inf)
        const float w0 = __expf(a0 - nm);
        const float w1 = __expf(a1 - nm);
        s = s * f + w0 + w1;
        accv.x = fmaf(w1, vv1.x, fmaf(w0, vv0.x, accv.x * f));
        accv.y = fmaf(w1, vv1.y, fmaf(w0, vv0.y, accv.y * f));
        accv.z = fmaf(w1, vv1.z, fmaf(w0, vv0.z, accv.z * f));
        accv.w = fmaf(w1, vv1.w, fmaf(w0, vv0.w, accv.w * f));
        acce.x = fmaf(w1, ea1.x, fmaf(w0, ea0.x, acce.x * f));
        acce.y = fmaf(w1, ea1.y, fmaf(w0, ea0.y, acce.y * f));
        m = nm;
    }
    if (p < end) {
        const int ei  = __ldg(&g_eorder[p]);
        const int src = clamp_node(__ldg(&edge_index[ei]));
        const float* s0 = g_proj + (size_t)src * 512;
        const float4 kv = __ldg((const float4*)(s0 + 128 + lane * 4));
        const float4 vv = __ldg((const float4*)(s0 + 256 + lane * 4));
        const float2 ea = __ldg((const float2*)(edge_attr + (size_t)ei * 64 + lane * 2));

        float d = fmaf(qv.x, kv.x, fmaf(qv.y, kv.y, fmaf(qv.z, kv.z,
                  fmaf(qv.w, kv.w, fmaf(qe.x, ea.x, qe.y * ea.y)))));
#pragma unroll
        for (int off = 16; off > 0; off >>= 1)
            d += __shfl_xor_sync(0xFFFFFFFFu, d, off);

        const float alpha = d * 0.08838834764831845f;
        const float nm = fmaxf(m, alpha);
        const float f  = __expf(m - nm);
        const float w  = __expf(alpha - nm);
        s = s * f + w;
        accv.x = fmaf(w, vv.x, accv.x * f);
        accv.y = fmaf(w, vv.y, accv.y * f);
        accv.z = fmaf(w, vv.z, accv.z * f);
        accv.w = fmaf(w, vv.w, accv.w * f);
        acce.x = fmaf(w, ea.x, acce.x * f);
        acce.y = fmaf(w, ea.y, acce.y * f);
        m = nm;
    }

    const float inv  = 1.0f / (s + 1e-16f);
    const float flag = (end > beg) ? 1.0f : 0.0f;
    const float4 bev = __ldg((const float4*)(be + lane * 4));

    float4 ov;
    ov.x = fmaf(accv.x, inv, flag * bev.x);
    ov.y = fmaf(accv.y, inv, flag * bev.y);
    ov.z = fmaf(accv.z, inv, flag * bev.z);
    ov.w = fmaf(accv.w, inv, flag * bev.w);
    *(float4*)(g_aggv + (size_t)node * 128 + lane * 4) = ov;

    float2 oe;
    oe.x = acce.x * inv;
    oe.y = acce.y * inv;
    *(float2*)(g_agge + (size_t)node * 64 + lane * 2) = oe;
}

// ---------------- launch ------------------------------------------------------
extern "C" void kernel_launch(void* const* d_in, const int* in_sizes, int n_in,
                              void* d_out, int out_size)
{
    const float* x    = (const float*)d_in[0];
    const int*   eidx = (const int*)d_in[1];
    const float* ea   = (const float*)d_in[2];
    const float* Wq   = (const float*)d_in[3];
    const float* bq   = (const float*)d_in[4];
    const float* Wk   = (const float*)d_in[5];
    const float* bk   = (const float*)d_in[6];
    const float* Wv   = (const float*)d_in[7];
    const float* bv   = (const float*)d_in[8];
    const float* We   = (const float*)d_in[9];
    const float* be   = (const float*)d_in[10];
    const float* Ws   = (const float*)d_in[11];
    const float* bs   = (const float*)d_in[12];
    float*       out  = (float*)d_out;

    cudaFuncSetAttribute(gemm_mma, cudaFuncAttributeMaxDynamicSharedMemorySize, MMA_SMEM);

    float *dproj, *dqe, *daggv, *dagge, *dbcat, *dWeT, *dzero;
    __nv_bfloat16 *dxh, *dxl, *dWTh, *dWTl;
    cudaGetSymbolAddress((void**)&dproj, g_proj);
    cudaGetSymbolAddress((void**)&dqe,   g_qe);
    cudaGetSymbolAddress((void**)&daggv, g_aggv);
    cudaGetSymbolAddress((void**)&dagge, g_agge);
    cudaGetSymbolAddress((void**)&dbcat, g_bcat);
    cudaGetSymbolAddress((void**)&dWeT,  g_WeT);
    cudaGetSymbolAddress((void**)&dzero, g_zero128);
    cudaGetSymbolAddress((void**)&dxh,   g_xhi);
    cudaGetSymbolAddress((void**)&dxl,   g_xlo);
    cudaGetSymbolAddress((void**)&dWTh,  g_WTh);
    cudaGetSymbolAddress((void**)&dWTl,  g_WTl);

    prep_weights<<<(512 * 256 + 255) / 256, 256>>>(Wq, Wk, Wv, Ws, bq, bk, bv, bs, We);  // 0
    split_x_kernel<<<(N_NODES * IN_SIZE / 4 + 255) / 256, 256>>>(x);                     // 1
    {
        dim3 grid(4, (N_NODES + 127) / 128);
        gemm_mma<<<grid, 256, MMA_SMEM>>>(dxh, dxl, dWTh, dWTl, dbcat, dproj);           // 2
    }
    // qe[M,64] = q[M,128] @ WeT[128,64] — sync-free small-K kernel (profiled slot 3)
    proj_small<16, 128, 64><<<(N_NODES + 15) / 16, 256>>>(
        dproj, 512, dWeT, dzero, dqe, 64,
        nullptr, 0, nullptr, 0, 0, N_NODES);                                             // 3
    count_kernel<<<(N_EDGES + 255) / 256, 256>>>(eidx);                                  // 4
    reduce_deg_kernel<<<SCAN_BLOCKS, 256>>>();                                           // 5
    scan_parts_kernel<<<1, 256>>>();                                                     // 6
    write_off_kernel<<<SCAN_BLOCKS, 256>>>();                                            // 7
    scatter_kernel<<<(N_EDGES + 255) / 256, 256>>>(eidx);                                // 8
    attn_kernel<<<(N_NODES + 7) / 8, 256>>>(eidx, ea, be);                               // 9
    // out = agge[M,64] @ We[64,128] + aggv + skip, then ELU
    proj_small<32, 64, 128><<<(N_NODES + 31) / 32, 256>>>(
        dagge, 64, We, dzero, out, 128,
        daggv, 128, dproj + 384, 512, 1, N_NODES);                                       // 10
}

// round 16
// speedup vs baseline: 1.4622x; 1.4622x over previous
#include <cuda_runtime.h>
#include <cuda_bf16.h>
#include <math.h>
#include <stdint.h>

#define N_NODES 50000
#define N_EDGES 800000
#define IN_SIZE 256
#define OUT_SIZE 128
#define EDGE_DIM 64
#define SCAN_BLOCKS ((N_NODES + 255) / 256)   // 196

// ---------------- scratch (static device globals; no runtime allocation) ----
__device__ float g_proj[(size_t)N_NODES * 512];          // rows: [q|k|v|skip], stride 512
__device__ float g_qe[(size_t)N_NODES * EDGE_DIM];
__device__ float g_aggv[(size_t)N_NODES * OUT_SIZE];
__device__ float g_agge[(size_t)N_NODES * EDGE_DIM];
__device__ __nv_bfloat16 g_xhi[(size_t)N_NODES * IN_SIZE];
__device__ __nv_bfloat16 g_xlo[(size_t)N_NODES * IN_SIZE];
__device__ __nv_bfloat16 g_WTh[512 * 256];               // [n=512][k=256] = Wcat^T hi
__device__ __nv_bfloat16 g_WTl[512 * 256];
__device__ float g_bcat[512];
__device__ float g_WeT[128 * 64];                        // [K=128][N=64] = We^T
__device__ float g_zero128[128];
__device__ int   g_deg[N_NODES];
__device__ int   g_off[N_NODES + 1];
__device__ int   g_cur[N_NODES];
__device__ int   g_eorder[N_EDGES];
__device__ int   g_part[SCAN_BLOCKS];

__device__ __forceinline__ int clamp_node(int v) {
    return (v < 0) ? 0 : ((v >= N_NODES) ? N_NODES - 1 : v);
}
__device__ __forceinline__ uint32_t smem_u32(const void* p) {
    uint32_t a;
    asm("{ .reg .u64 t; cvta.to.shared.u64 t, %1; cvt.u32.u64 %0, t; }" : "=r"(a) : "l"(p));
    return a;
}

#define CPASYNC16(saddr, gptr) \
    asm volatile("cp.async.cg.shared.global [%0], [%1], 16;" :: "r"(saddr), "l"(gptr))
#define CP_COMMIT() asm volatile("cp.async.commit_group;" ::: "memory")
#define LDM4(d, addr) \
    asm volatile("ldmatrix.sync.aligned.m8n8.x4.shared.b16 {%0,%1,%2,%3}, [%4];" \
        : "=r"((d)[0]), "=r"((d)[1]), "=r"((d)[2]), "=r"((d)[3]) : "r"(addr))
#define MMA16816(c, a, b0v, b1v) \
    asm volatile("mma.sync.aligned.m16n8k16.row.col.f32.bf16.bf16.f32 " \
        "{%0,%1,%2,%3}, {%4,%5,%6,%7}, {%8,%9}, {%0,%1,%2,%3};" \
        : "+f"((c)[0]), "+f"((c)[1]), "+f"((c)[2]), "+f"((c)[3]) \
        : "r"((a)[0]), "r"((a)[1]), "r"((a)[2]), "r"((a)[3]), "r"(b0v), "r"(b1v))

// ---------------- bf16x3 tensor-core GEMM for node projections ---------------
#define NSTAGE 8            // 256 / 32
#define SROWB  80           // bytes per row slot (32 bf16 + 8 pad)
#define OFF_AH 0
#define OFF_AL 10240
#define OFF_BH 20480
#define OFF_BL 30720
#define BUFSZ  40960
#define MMA_SMEM (2 * BUFSZ)   // 81920

__global__ __launch_bounds__(256, 2) void gemm_mma(
    const __nv_bfloat16* __restrict__ Ahg, const __nv_bfloat16* __restrict__ Alg,
    const __nv_bfloat16* __restrict__ Bhg, const __nv_bfloat16* __restrict__ Blg,
    const float* __restrict__ bias, float* __restrict__ C)
{
    extern __shared__ char sm[];
    const uint32_t sb = smem_u32(sm);
    const int tid  = threadIdx.x;
    const int lane = tid & 31, wid = tid >> 5;
    const int wm = wid >> 1, wn = wid & 1;        // 4 x 2 warp grid
    const int row0 = blockIdx.y * 128;
    const int col0 = blockIdx.x * 128;

    float acc[2][8][4];
#pragma unroll
    for (int m = 0; m < 2; m++)
#pragma unroll
        for (int n = 0; n < 8; n++)
#pragma unroll
            for (int i = 0; i < 4; i++) acc[m][n][i] = 0.f;

    const int r8  = lane & 7, grp = lane >> 3;
    const int aRow = wm * 32 + ((grp & 1) << 3) + r8;
    const int aKel = (grp >> 1) << 3;
    const int bRow = wn * 64 + ((grp >> 1) << 3) + r8;
    const int bKel = (grp & 1) << 3;

#define LOAD_STAGE(s) do {                                                      \
        const int k0 = (s) * 32;                                                \
        const uint32_t bb = sb + ((s) & 1) * BUFSZ;                             \
        _Pragma("unroll")                                                       \
        for (int c = 0; c < 2; c++) {                                           \
            int idx = tid * 2 + c;                                              \
            int row = idx >> 2, sub = idx & 3;                                  \
            int gr = row0 + row; if (gr >= N_NODES) gr = N_NODES - 1;           \
            size_t gaoff = (size_t)gr * IN_SIZE + k0 + sub * 8;                 \
            uint32_t soff = row * SROWB + sub * 16;                             \
            CPASYNC16(bb + OFF_AH + soff, Ahg + gaoff);                         \
            CPASYNC16(bb + OFF_AL + soff, Alg + gaoff);                         \
            size_t gboff = (size_t)(col0 + row) * IN_SIZE + k0 + sub * 8;       \
            CPASYNC16(bb + OFF_BH + soff, Bhg + gboff);                         \
            CPASYNC16(bb + OFF_BL + soff, Blg + gboff);                         \
        }                                                                       \
        CP_COMMIT();                                                            \
    } while (0)

    LOAD_STAGE(0);

    for (int s = 0; s < NSTAGE; s++) {
        if (s + 1 < NSTAGE) {
            LOAD_STAGE(s + 1);
            asm volatile("cp.async.wait_group 1;" ::: "memory");
        } else {
            asm volatile("cp.async.wait_group 0;" ::: "memory");
        }
        __syncthreads();

        const uint32_t bb = sb + (s & 1) * BUFSZ;
#pragma unroll
        for (int ks = 0; ks < 32; ks += 16) {
            uint32_t ah[2][4], al[2][4];
#pragma unroll
            for (int mt = 0; mt < 2; mt++) {
                uint32_t ad = bb + OFF_AH + (aRow + mt * 16) * SROWB + (aKel + ks) * 2;
                LDM4(ah[mt], ad);
                LDM4(al[mt], ad + (OFF_AL - OFF_AH));
            }
#pragma unroll
            for (int p = 0; p < 4; p++) {
                uint32_t bh[4], bl[4];
                uint32_t bd = bb + OFF_BH + (bRow + p * 16) * SROWB + (bKel + ks) * 2;
                LDM4(bh, bd);
                LDM4(bl, bd + (OFF_BL - OFF_BH));
#pragma unroll
                for (int mt = 0; mt < 2; mt++) {
#pragma unroll
                    for (int t = 0; t < 2; t++) {
                        float* cc = acc[mt][p * 2 + t];
                        MMA16816(cc, ah[mt], bh[2 * t], bh[2 * t + 1]);
                        MMA16816(cc, ah[mt], bl[2 * t], bl[2 * t + 1]);
                        MMA16816(cc, al[mt], bh[2 * t], bh[2 * t + 1]);
                    }
                }
            }
        }
        __syncthreads();
    }

#pragma unroll
    for (int mt = 0; mt < 2; mt++) {
        int r = row0 + wm * 32 + mt * 16 + (lane >> 2);
#pragma unroll
        for (int p = 0; p < 8; p++) {
            int col = col0 + wn * 64 + p * 8 + (lane & 3) * 2;
            float b0 = __ldg(bias + col), b1 = __ldg(bias + col + 1);
            if (r < N_NODES) {
                float2 o = make_float2(acc[mt][p][0] + b0, acc[mt][p][1] + b1);
                *(float2*)(C + (size_t)r * 512 + col) = o;
            }
            if (r + 8 < N_NODES) {
                float2 o = make_float2(acc[mt][p][2] + b0, acc[mt][p][3] + b1);
                *(float2*)(C + (size_t)(r + 8) * 512 + col) = o;
            }
        }
    }
#undef LOAD_STAGE
}

// ---------------- small-K projection GEMM v2: 2D register tiles ---------------
// C[M,N] = A[M,K](lda) @ B[K,N] + bias (+add1/+add2, elu). 256 threads.
// 64-row blocks, 16x16 thread grid, thread tile = 4 rows x (N/16) cols.
// One __syncthreads; B and A-block fully staged in dynamic smem.
template <int K, int N>
__global__ __launch_bounds__(256) void proj_small(
    const float* __restrict__ A, int lda,
    const float* __restrict__ B,
    const float* __restrict__ bias, float* __restrict__ C, int ldc,
    const float* __restrict__ add1, int as1,
    const float* __restrict__ add2, int as2,
    int do_elu, int M)
{
    constexpr int ROWS = 64;
    constexpr int RT = 4;                 // rows per thread
    constexpr int CT = N / 16;            // cols per thread
    static_assert(CT % 4 == 0, "float4 tiles");
    constexpr int KP = K + 4;             // padded A row

    extern __shared__ float smf[];
    float* Bs = smf;                      // [K * N]
    float* As = smf + K * N;              // [ROWS * KP]

    const int tid  = threadIdx.x;
    const int row0 = blockIdx.x * ROWS;

    // stage B (coalesced float4)
#pragma unroll
    for (int i = 0; i < (K * N) / (256 * 4); i++) {
        int f = tid + i * 256;
        *(float4*)&Bs[f * 4] = *(const float4*)(B + f * 4);
    }
    // stage A rows (guarded)
#pragma unroll
    for (int i = 0; i < (ROWS * K) / (256 * 4); i++) {
        int f = tid + i * 256;
        int r = f / (K / 4);
        int kk = (f % (K / 4)) * 4;
        int gr = row0 + r;
        float4 v = make_float4(0.f, 0.f, 0.f, 0.f);
        if (gr < M) v = *(const float4*)(A + (size_t)gr * lda + kk);
        *(float4*)&As[r * KP + kk] = v;
    }
    __syncthreads();

    const int r0 = (tid / 16) * RT;       // thread's first row
    const int c0 = (tid % 16) * CT;       // thread's first col

    float acc[RT][CT];
#pragma unroll
    for (int i = 0; i < RT; i++)
#pragma unroll
        for (int j = 0; j < CT; j++) acc[i][j] = 0.f;

#pragma unroll 4
    for (int k = 0; k < K; k++) {
        float regM[RT];
#pragma unroll
        for (int i = 0; i < RT; i++) regM[i] = As[(r0 + i) * KP + k];
        float regN[CT];
#pragma unroll
        for (int j = 0; j < CT; j += 4)
            *(float4*)&regN[j] = *(float4*)&Bs[k * N + c0 + j];
#pragma unroll
        for (int i = 0; i < RT; i++)
#pragma unroll
            for (int j = 0; j < CT; j++)
                acc[i][j] = fmaf(regM[i], regN[j], acc[i][j]);
    }

#pragma unroll
    for (int i = 0; i < RT; i++) {
        const int gr = row0 + r0 + i;
        if (gr >= M) continue;
#pragma unroll
        for (int j = 0; j < CT; j += 4) {
            int c = c0 + j;
            float4 o;
            o.x = acc[i][j + 0] + bias[c + 0];
            o.y = acc[i][j + 1] + bias[c + 1];
            o.z = acc[i][j + 2] + bias[c + 2];
            o.w = acc[i][j + 3] + bias[c + 3];
            if (add1) {
                float4 a1 = *(const float4*)(add1 + (size_t)gr * as1 + c);
                o.x += a1.x; o.y += a1.y; o.z += a1.z; o.w += a1.w;
            }
            if (add2) {
                float4 a2 = *(const float4*)(add2 + (size_t)gr * as2 + c);
                o.x += a2.x; o.y += a2.y; o.z += a2.z; o.w += a2.w;
            }
            if (do_elu) {
                o.x = (o.x > 0.f) ? o.x : expm1f(o.x);
                o.y = (o.y > 0.f) ? o.y : expm1f(o.y);
                o.z = (o.z > 0.f) ? o.z : expm1f(o.z);
                o.w = (o.w > 0.f) ? o.w : expm1f(o.w);
            }
            *(float4*)(C + (size_t)gr * ldc + c) = o;
        }
    }
}

#define QE_SMEM  ((128 * 64 + 64 * 132) * 4)   // 66560 B
#define FIN_SMEM ((64 * 128 + 64 * 68) * 4)    // 50176 B

// ---------------- prep kernels ------------------------------------------------
__global__ void split_x_kernel(const float* __restrict__ x) {
    int i = blockIdx.x * blockDim.x + threadIdx.x;
    if (i < N_NODES * IN_SIZE / 4) {
        float4 v = ((const float4*)x)[i];
        __nv_bfloat16 hx = __float2bfloat16(v.x), hy = __float2bfloat16(v.y);
        __nv_bfloat16 hz = __float2bfloat16(v.z), hw = __float2bfloat16(v.w);
        __nv_bfloat16 lx = __float2bfloat16(v.x - __bfloat162float(hx));
        __nv_bfloat16 ly = __float2bfloat16(v.y - __bfloat162float(hy));
        __nv_bfloat16 lz = __float2bfloat16(v.z - __bfloat162float(hz));
        __nv_bfloat16 lw = __float2bfloat16(v.w - __bfloat162float(hw));
        __nv_bfloat162 h01 = __halves2bfloat162(hx, hy), h23 = __halves2bfloat162(hz, hw);
        __nv_bfloat162 l01 = __halves2bfloat162(lx, ly), l23 = __halves2bfloat162(lz, lw);
        ((uint2*)g_xhi)[i] = make_uint2(*(uint32_t*)&h01, *(uint32_t*)&h23);
        ((uint2*)g_xlo)[i] = make_uint2(*(uint32_t*)&l01, *(uint32_t*)&l23);
    }
}

__global__ void prep_weights(const float* __restrict__ Wq, const float* __restrict__ Wk,
                             const float* __restrict__ Wv, const float* __restrict__ Ws,
                             const float* __restrict__ bq, const float* __restrict__ bk,
                             const float* __restrict__ bv, const float* __restrict__ bs,
                             const float* __restrict__ We) {
    int idx = blockIdx.x * blockDim.x + threadIdx.x;
    if (idx < 512 * 256) {
        int col = idx / 256, k = idx % 256;
        int g = col / 128, n = col % 128;
        const float* W = (g == 0) ? Wq : (g == 1) ? Wk : (g == 2) ? Wv : Ws;
        float v = W[k * 128 + n];
        __nv_bfloat16 hi = __float2bfloat16(v);
        __nv_bfloat16 lo = __float2bfloat16(v - __bfloat162float(hi));
        g_WTh[col * 256 + k] = hi;
        g_WTl[col * 256 + k] = lo;
    }
    if (idx < 512) {
        const float* b = (idx < 128) ? bq : (idx < 256) ? bk : (idx < 384) ? bv : bs;
        g_bcat[idx] = b[idx % 128];
    }
    if (idx < 128 * 64) {
        int c = idx / 64, d = idx % 64;
        g_WeT[c * 64 + d] = We[d * 128 + c];
    }
    if (idx < 128) g_zero128[idx] = 0.f;
    if (idx < N_NODES) g_deg[idx] = 0;     // fused zero_deg
}

// ---------------- CSR build ---------------------------------------------------
__global__ void count_kernel(const int* __restrict__ edge_index) {
    int i = blockIdx.x * blockDim.x + threadIdx.x;
    if (i < N_EDGES) atomicAdd(&g_deg[clamp_node(edge_index[N_EDGES + i])], 1);
}
__global__ __launch_bounds__(256) void reduce_deg_kernel() {
    __shared__ int sm[256];
    int t = threadIdx.x;
    int i = blockIdx.x * 256 + t;
    sm[t] = (i < N_NODES) ? g_deg[i] : 0;
    __syncthreads();
#pragma unroll
    for (int s = 128; s > 0; s >>= 1) {
        if (t < s) sm[t] += sm[t + s];
        __syncthreads();
    }
    if (t == 0) g_part[blockIdx.x] = sm[0];
}
__global__ __launch_bounds__(256) void scan_parts_kernel() {
    __shared__ int sp[256];
    int t = threadIdx.x;
    int v = (t < SCAN_BLOCKS) ? g_part[t] : 0;
    sp[t] = v;
    __syncthreads();
#pragma unroll
    for (int off = 1; off < 256; off <<= 1) {
        int u = (t >= off) ? sp[t - off] : 0;
        __syncthreads();
        sp[t] += u;
        __syncthreads();
    }
    if (t < SCAN_BLOCKS) g_part[t] = sp[t] - v;
}
__global__ __launch_bounds__(256) void write_off_kernel() {
    __shared__ int sc[256];
    int t = threadIdx.x;
    int i = blockIdx.x * 256 + t;
    int d = (i < N_NODES) ? g_deg[i] : 0;
    sc[t] = d;
    __syncthreads();
#pragma unroll
    for (int off = 1; off < 256; off <<= 1) {
        int u = (t >= off) ? sc[t - off] : 0;
        __syncthreads();
        sc[t] += u;
        __syncthreads();
    }
    int excl = sc[t] - d + g_part[blockIdx.x];
    if (i < N_NODES) {
        g_off[i] = excl;
        g_cur[i] = excl;
        if (i == N_NODES - 1) g_off[N_NODES] = excl + d;
    }
}
__global__ void scatter_kernel(const int* __restrict__ edge_index) {
    int i = blockIdx.x * blockDim.x + threadIdx.x;
    if (i < N_EDGES) {
        int dst = clamp_node(edge_index[N_EDGES + i]);
        int p = atomicAdd(&g_cur[dst], 1);
        if (p >= 0 && p < N_EDGES) g_eorder[p] = i;
    }
}

// ---------------- fused attention (R8: one warp/node, 2-edge unrolled) --------
__global__ __launch_bounds__(256) void attn_kernel(
    const int* __restrict__ edge_index, const float* __restrict__ edge_attr,
    const float* __restrict__ be)
{
    const int warp = threadIdx.x / 32;
    const int lane = threadIdx.x % 32;
    const int node = blockIdx.x * 8 + warp;
    if (node >= N_NODES) return;

    const float* prow = g_proj + (size_t)node * 512;
    const float4 qv = __ldg((const float4*)(prow + lane * 4));
    const float2 qe = __ldg((const float2*)(g_qe + (size_t)node * 64 + lane * 2));

    float4 accv = make_float4(0.f, 0.f, 0.f, 0.f);
    float2 acce = make_float2(0.f, 0.f);
    float m = -INFINITY;
    float s = 0.f;

    int beg = g_off[node];
    int end = g_off[node + 1];
    if (beg < 0) beg = 0;
    if (end > N_EDGES) end = N_EDGES;

    int p = beg;
    for (; p + 1 < end; p += 2) {
        const int ei0  = __ldg(&g_eorder[p]);
        const int ei1  = __ldg(&g_eorder[p + 1]);
        const int src0 = clamp_node(__ldg(&edge_index[ei0]));
        const int src1 = clamp_node(__ldg(&edge_index[ei1]));

        const float* s0 = g_proj + (size_t)src0 * 512;
        const float* s1 = g_proj + (size_t)src1 * 512;
        const float4 kv0 = __ldg((const float4*)(s0 + 128 + lane * 4));
        const float4 kv1 = __ldg((const float4*)(s1 + 128 + lane * 4));
        const float4 vv0 = __ldg((const float4*)(s0 + 256 + lane * 4));
        const float4 vv1 = __ldg((const float4*)(s1 + 256 + lane * 4));
        const float2 ea0 = __ldg((const float2*)(edge_attr + (size_t)ei0 * 64 + lane * 2));
        const float2 ea1 = __ldg((const float2*)(edge_attr + (size_t)ei1 * 64 + lane * 2));

        float d0 = fmaf(qv.x, kv0.x, fmaf(qv.y, kv0.y, fmaf(qv.z, kv0.z,
                   fmaf(qv.w, kv0.w, fmaf(qe.x, ea0.x, qe.y * ea0.y)))));
        float d1 = fmaf(qv.x, kv1.x, fmaf(qv.y, kv1.y, fmaf(qv.z, kv1.z,
                   fmaf(qv.w, kv1.w, fmaf(qe.x, ea1.x, qe.y * ea1.y)))));
#pragma unroll
        for (int off = 16; off > 0; off >>= 1) {
            d0 += __shfl_xor_sync(0xFFFFFFFFu, d0, off);
            d1 += __shfl_xor_sync(0xFFFFFFFFu, d1, off);
        }

        const float a0 = d0 * 0.08838834764831845f;   // 1/sqrt(128)
        const float a1 = d1 * 0.08838834764831845f;
        const float nm = fmaxf(m, fmaxf(a0, a1));
        const float f  = __expf(m - nm);              // 0 on first pair (m = -inf)
        const float w0 = __expf(a0 - nm);
        const float w1 = __expf(a1 - nm);
        s = s * f + w0 + w1;
        accv.x = fmaf(w1, vv1.x, fmaf(w0, vv0.x, accv.x * f));
        accv.y = fmaf(w1, vv1.y, fmaf(w0, vv0.y, accv.y * f));
        accv.z = fmaf(w1, vv1.z, fmaf(w0, vv0.z, accv.z * f));
        accv.w = fmaf(w1, vv1.w, fmaf(w0, vv0.w, accv.w * f));
        acce.x = fmaf(w1, ea1.x, fmaf(w0, ea0.x, acce.x * f));
        acce.y = fmaf(w1, ea1.y, fmaf(w0, ea0.y, acce.y * f));
        m = nm;
    }
    if (p < end) {
        const int ei  = __ldg(&g_eorder[p]);
        const int src = clamp_node(__ldg(&edge_index[ei]));
        const float* s0 = g_proj + (size_t)src * 512;
        const float4 kv = __ldg((const float4*)(s0 + 128 + lane * 4));
        const float4 vv = __ldg((const float4*)(s0 + 256 + lane * 4));
        const float2 ea = __ldg((const float2*)(edge_attr + (size_t)ei * 64 + lane * 2));

        float d = fmaf(qv.x, kv.x, fmaf(qv.y, kv.y, fmaf(qv.z, kv.z,
                  fmaf(qv.w, kv.w, fmaf(qe.x, ea.x, qe.y * ea.y)))));
#pragma unroll
        for (int off = 16; off > 0; off >>= 1)
            d += __shfl_xor_sync(0xFFFFFFFFu, d, off);

        const float alpha = d * 0.08838834764831845f;
        const float nm = fmaxf(m, alpha);
        const float f  = __expf(m - nm);
        const float w  = __expf(alpha - nm);
        s = s * f + w;
        accv.x = fmaf(w, vv.x, accv.x * f);
        accv.y = fmaf(w, vv.y, accv.y * f);
        accv.z = fmaf(w, vv.z, accv.z * f);
        accv.w = fmaf(w, vv.w, accv.w * f);
        acce.x = fmaf(w, ea.x, acce.x * f);
        acce.y = fmaf(w, ea.y, acce.y * f);
        m = nm;
    }

    const float inv  = 1.0f / (s + 1e-16f);
    const float flag = (end > beg) ? 1.0f : 0.0f;
    const float4 bev = __ldg((const float4*)(be + lane * 4));

    float4 ov;
    ov.x = fmaf(accv.x, inv, flag * bev.x);
    ov.y = fmaf(accv.y, inv, flag * bev.y);
    ov.z = fmaf(accv.z, inv, flag * bev.z);
    ov.w = fmaf(accv.w, inv, flag * bev.w);
    *(float4*)(g_aggv + (size_t)node * 128 + lane * 4) = ov;

    float2 oe;
    oe.x = acce.x * inv;
    oe.y = acce.y * inv;
    *(float2*)(g_agge + (size_t)node * 64 + lane * 2) = oe;
}

// ---------------- launch ------------------------------------------------------
extern "C" void kernel_launch(void* const* d_in, const int* in_sizes, int n_in,
                              void* d_out, int out_size)
{
    const float* x    = (const float*)d_in[0];
    const int*   eidx = (const int*)d_in[1];
    const float* ea   = (const float*)d_in[2];
    const float* Wq   = (const float*)d_in[3];
    const float* bq   = (const float*)d_in[4];
    const float* Wk   = (const float*)d_in[5];
    const float* bk   = (const float*)d_in[6];
    const float* Wv   = (const float*)d_in[7];
    const float* bv   = (const float*)d_in[8];
    const float* We   = (const float*)d_in[9];
    const float* be   = (const float*)d_in[10];
    const float* Ws   = (const float*)d_in[11];
    const float* bs   = (const float*)d_in[12];
    float*       out  = (float*)d_out;

    cudaFuncSetAttribute(gemm_mma, cudaFuncAttributeMaxDynamicSharedMemorySize, MMA_SMEM);
    cudaFuncSetAttribute(proj_small<128, 64>,
                         cudaFuncAttributeMaxDynamicSharedMemorySize, QE_SMEM);
    cudaFuncSetAttribute(proj_small<64, 128>,
                         cudaFuncAttributeMaxDynamicSharedMemorySize, FIN_SMEM);

    float *dproj, *dqe, *daggv, *dagge, *dbcat, *dWeT, *dzero;
    __nv_bfloat16 *dxh, *dxl, *dWTh, *dWTl;
    cudaGetSymbolAddress((void**)&dproj, g_proj);
    cudaGetSymbolAddress((void**)&dqe,   g_qe);
    cudaGetSymbolAddress((void**)&daggv, g_aggv);
    cudaGetSymbolAddress((void**)&dagge, g_agge);
    cudaGetSymbolAddress((void**)&dbcat, g_bcat);
    cudaGetSymbolAddress((void**)&dWeT,  g_WeT);
    cudaGetSymbolAddress((void**)&dzero, g_zero128);
    cudaGetSymbolAddress((void**)&dxh,   g_xhi);
    cudaGetSymbolAddress((void**)&dxl,   g_xlo);
    cudaGetSymbolAddress((void**)&dWTh,  g_WTh);
    cudaGetSymbolAddress((void**)&dWTl,  g_WTl);

    prep_weights<<<(512 * 256 + 255) / 256, 256>>>(Wq, Wk, Wv, Ws, bq, bk, bv, bs, We);  // 0
    split_x_kernel<<<(N_NODES * IN_SIZE / 4 + 255) / 256, 256>>>(x);                     // 1
    {
        dim3 grid(4, (N_NODES + 127) / 128);
        gemm_mma<<<grid, 256, MMA_SMEM>>>(dxh, dxl, dWTh, dWTl, dbcat, dproj);           // 2
    }
    // qe[M,64] = q[M,128] @ WeT[128,64] — 2D-tiled small-K kernel (profiled slot 3)
    proj_small<128, 64><<<(N_NODES + 63) / 64, 256, QE_SMEM>>>(
        dproj, 512, dWeT, dzero, dqe, 64,
        nullptr, 0, nullptr, 0, 0, N_NODES);                                             // 3
    count_kernel<<<(N_EDGES + 255) / 256, 256>>>(eidx);                                  // 4
    reduce_deg_kernel<<<SCAN_BLOCKS, 256>>>();                                           // 5
    scan_parts_kernel<<<1, 256>>>();                                                     // 6
    write_off_kernel<<<SCAN_BLOCKS, 256>>>();                                            // 7
    scatter_kernel<<<(N_EDGES + 255) / 256, 256>>>(eidx);                                // 8
    attn_kernel<<<(N_NODES + 7) / 8, 256>>>(eidx, ea, be);                               // 9
    // out = agge[M,64] @ We[64,128] + aggv + skip, then ELU
    proj_small<64, 128><<<(N_NODES + 63) / 64, 256, FIN_SMEM>>>(
        dagge, 64, We, dzero, out, 128,
        daggv, 128, dproj + 384, 512, 1, N_NODES);                                       // 10
}